// round 1
// baseline (speedup 1.0000x reference)
#include <cuda_runtime.h>

// ---------------------------------------------------------------------------
// Problem constants: B=4, L=2048, D=1024
// Outputs (fp32), concatenated in reference return order:
//   out (4,2048,1024)      = 8388608
//   res (4,2048,1,2048)    = 16777216
//   a2  (4,2048,2048)      = 16777216
// ---------------------------------------------------------------------------

#define SZB 8388608ull          // 8192*1024 floats, one (B,L,D) buffer
#define SSB 16777216ull         // 4*2048*2048 floats, one (B,L,L) buffer

// Scratch: q1, k, v, nq, nk, nv, oatt, o1, q2  (9 x SZB) + S (SSB)
__device__ float g_buf[9ull * SZB + SSB];

// ---------------------------------------------------------------------------
// SGEMM: C = scale * (A @ B[^T]) (+ bias), row-major.
//   A: M x K (row stride K)
//   NT=false: B is K x N (row stride N)   -> C = A @ B
//   NT=true : B is N x K (row stride K)   -> C = A @ B^T
// 128x128x8 tile, 256 threads, 8x8 micro-tile. Batched via blockIdx.z.
// ---------------------------------------------------------------------------
constexpr int BM = 128, BN = 128, BK = 8, TM = 8, TN = 8;

template <bool NT, bool BIAS>
__global__ void __launch_bounds__(256) gemm_k(
    const float* __restrict__ A, const float* __restrict__ Bm,
    const float* __restrict__ bias, float* __restrict__ C,
    int M, int N, int K, float scale,
    long long sA, long long sB, long long sC)
{
    __shared__ float As[BK][BM];
    __shared__ float Bs[BK][BN];

    const int bz = blockIdx.z;
    A  += (long long)bz * sA;
    Bm += (long long)bz * sB;
    C  += (long long)bz * sC;

    const int m0 = blockIdx.y * BM;
    const int n0 = blockIdx.x * BN;
    const int tid = threadIdx.x;
    const int tx = tid & 15;        // 16 cols of threads
    const int ty = tid >> 4;        // 16 rows of threads
    const int arow = tid >> 1;      // 128 rows, 2 threads/row
    const int ac4  = (tid & 1) * 4; // float4 within 8-wide k slab
    const int brow = tid >> 5;      // 8 k-rows (NN load)
    const int bc4  = (tid & 31) * 4;

    float acc[TM][TN] = {};

    for (int k0 = 0; k0 < K; k0 += BK) {
        // load A tile (128 x 8), store transposed As[k][m]
        float4 av = *(const float4*)(A + (long long)(m0 + arow) * K + k0 + ac4);
        As[ac4 + 0][arow] = av.x;
        As[ac4 + 1][arow] = av.y;
        As[ac4 + 2][arow] = av.z;
        As[ac4 + 3][arow] = av.w;

        if (NT) {
            // B tile: rows n0..n0+127, cols k0..k0+7 (B row stride = K)
            float4 bv = *(const float4*)(Bm + (long long)(n0 + arow) * K + k0 + ac4);
            Bs[ac4 + 0][arow] = bv.x;
            Bs[ac4 + 1][arow] = bv.y;
            Bs[ac4 + 2][arow] = bv.z;
            Bs[ac4 + 3][arow] = bv.w;
        } else {
            // B tile: rows k0..k0+7, cols n0..n0+127 (B row stride = N)
            *(float4*)&Bs[brow][bc4] =
                *(const float4*)(Bm + (long long)(k0 + brow) * N + n0 + bc4);
        }
        __syncthreads();

#pragma unroll
        for (int kk = 0; kk < BK; kk++) {
            float a[TM], b[TN];
#pragma unroll
            for (int i = 0; i < TM; i++) a[i] = As[kk][ty * TM + i];
#pragma unroll
            for (int j = 0; j < TN; j++) b[j] = Bs[kk][tx * TN + j];
#pragma unroll
            for (int i = 0; i < TM; i++)
#pragma unroll
                for (int j = 0; j < TN; j++)
                    acc[i][j] += a[i] * b[j];
        }
        __syncthreads();
    }

#pragma unroll
    for (int i = 0; i < TM; i++) {
        const int row = m0 + ty * TM + i;
#pragma unroll
        for (int j = 0; j < TN; j += 4) {
            const int col = n0 + tx * TN + j;
            float4 o;
            o.x = acc[i][j + 0] * scale;
            o.y = acc[i][j + 1] * scale;
            o.z = acc[i][j + 2] * scale;
            o.w = acc[i][j + 3] * scale;
            if (BIAS) {
                o.x += bias[col + 0];
                o.y += bias[col + 1];
                o.z += bias[col + 2];
                o.w += bias[col + 3];
            }
            *(float4*)(C + (long long)row * N + col) = o;
        }
    }
}

// ---------------------------------------------------------------------------
// LayerNorm over rows of 1024 floats. One block (256 threads) per row.
// ---------------------------------------------------------------------------
__global__ void __launch_bounds__(256) ln_k(
    const float* __restrict__ x, const float* __restrict__ g,
    const float* __restrict__ b, float* __restrict__ y)
{
    const long long row = blockIdx.x;
    const float4 v = ((const float4*)(x + row * 1024))[threadIdx.x];

    float s  = v.x + v.y + v.z + v.w;
    float s2 = v.x * v.x + v.y * v.y + v.z * v.z + v.w * v.w;

    __shared__ float sh[8], sh2[8];
#pragma unroll
    for (int o = 16; o > 0; o >>= 1) {
        s  += __shfl_xor_sync(0xffffffffu, s, o);
        s2 += __shfl_xor_sync(0xffffffffu, s2, o);
    }
    const int lane = threadIdx.x & 31, warp = threadIdx.x >> 5;
    if (lane == 0) { sh[warp] = s; sh2[warp] = s2; }
    __syncthreads();
    float S = 0.f, S2 = 0.f;
#pragma unroll
    for (int i = 0; i < 8; i++) { S += sh[i]; S2 += sh2[i]; }

    const float mean = S * (1.0f / 1024.0f);
    const float var  = S2 * (1.0f / 1024.0f) - mean * mean;
    const float inv  = rsqrtf(var + 1e-6f);

    const float4 gg = ((const float4*)g)[threadIdx.x];
    const float4 bb = ((const float4*)b)[threadIdx.x];
    float4 o;
    o.x = (v.x - mean) * inv * gg.x + bb.x;
    o.y = (v.y - mean) * inv * gg.y + bb.y;
    o.z = (v.z - mean) * inv * gg.z + bb.z;
    o.w = (v.w - mean) * inv * gg.w + bb.w;
    ((float4*)(y + row * 1024))[threadIdx.x] = o;
}

// ---------------------------------------------------------------------------
// In-place row softmax, rows of 2048 floats. One block (256 threads) per row.
// ---------------------------------------------------------------------------
__global__ void __launch_bounds__(256) softmax_k(float* __restrict__ S)
{
    const long long row = blockIdx.x;
    float* r = S + row * 2048;
    const int base = threadIdx.x * 8;

    float v[8];
    float4 a = *(const float4*)(r + base);
    float4 c = *(const float4*)(r + base + 4);
    v[0] = a.x; v[1] = a.y; v[2] = a.z; v[3] = a.w;
    v[4] = c.x; v[5] = c.y; v[6] = c.z; v[7] = c.w;

    float mx = v[0];
#pragma unroll
    for (int i = 1; i < 8; i++) mx = fmaxf(mx, v[i]);

    __shared__ float shm[8], shs[8];
#pragma unroll
    for (int o = 16; o > 0; o >>= 1) mx = fmaxf(mx, __shfl_xor_sync(0xffffffffu, mx, o));
    const int lane = threadIdx.x & 31, warp = threadIdx.x >> 5;
    if (lane == 0) shm[warp] = mx;
    __syncthreads();
    float M = shm[0];
#pragma unroll
    for (int i = 1; i < 8; i++) M = fmaxf(M, shm[i]);

    float sum = 0.f;
#pragma unroll
    for (int i = 0; i < 8; i++) { v[i] = __expf(v[i] - M); sum += v[i]; }
#pragma unroll
    for (int o = 16; o > 0; o >>= 1) sum += __shfl_xor_sync(0xffffffffu, sum, o);
    if (lane == 0) shs[warp] = sum;
    __syncthreads();
    float T = 0.f;
#pragma unroll
    for (int i = 0; i < 8; i++) T += shs[i];

    const float inv = 1.0f / T;
    a.x = v[0] * inv; a.y = v[1] * inv; a.z = v[2] * inv; a.w = v[3] * inv;
    c.x = v[4] * inv; c.y = v[5] * inv; c.z = v[6] * inv; c.w = v[7] * inv;
    *(float4*)(r + base)     = a;
    *(float4*)(r + base + 4) = c;
}

// ---------------------------------------------------------------------------
// res = concat(q1, q2) along last dim: (8192 rows, 2048 cols)
// ---------------------------------------------------------------------------
__global__ void __launch_bounds__(256) res_k(
    const float* __restrict__ q1, const float* __restrict__ q2,
    float* __restrict__ res)
{
    const long long i = (long long)blockIdx.x * blockDim.x + threadIdx.x; // float4 idx
    const long long e = i * 4;
    const long long row = e >> 11;        // /2048
    const int c = (int)(e & 2047);
    const float* src = (c < 1024) ? (q1 + row * 1024 + c)
                                  : (q2 + row * 1024 + (c - 1024));
    *(float4*)(res + e) = *(const float4*)src;
}

// ---------------------------------------------------------------------------
extern "C" void kernel_launch(void* const* d_in, const int* in_sizes, int n_in,
                              void* d_out, int out_size)
{
    const float* q   = (const float*)d_in[0];
    const float* k   = (const float*)d_in[1];
    const float* v   = (const float*)d_in[2];
    const float* Wq1 = (const float*)d_in[3];
    const float* bq1 = (const float*)d_in[4];
    const float* Wk1 = (const float*)d_in[5];
    const float* bk1 = (const float*)d_in[6];
    const float* Wv1 = (const float*)d_in[7];
    const float* bv1 = (const float*)d_in[8];
    const float* Wf1 = (const float*)d_in[9];
    const float* bf1 = (const float*)d_in[10];
    const float* Wq2 = (const float*)d_in[11];
    const float* bq2 = (const float*)d_in[12];
    const float* Wk2 = (const float*)d_in[13];
    const float* bk2 = (const float*)d_in[14];
    const float* Wv2 = (const float*)d_in[15];
    const float* bv2 = (const float*)d_in[16];
    const float* Wf2 = (const float*)d_in[17];
    const float* bf2 = (const float*)d_in[18];
    const float* gq1 = (const float*)d_in[19];
    const float* Bq1 = (const float*)d_in[20];
    const float* gk1 = (const float*)d_in[21];
    const float* Bk1 = (const float*)d_in[22];
    const float* gv1 = (const float*)d_in[23];
    const float* Bv1 = (const float*)d_in[24];
    const float* gq2 = (const float*)d_in[25];
    const float* Bq2 = (const float*)d_in[26];
    const float* gk2 = (const float*)d_in[27];
    const float* Bk2 = (const float*)d_in[28];
    const float* gv2 = (const float*)d_in[29];
    const float* Bv2 = (const float*)d_in[30];

    float* out = (float*)d_out;           // 8388608
    float* res = out + SZB;               // 16777216
    float* a2  = res + SSB;               // 16777216

    float* buf = nullptr;
    cudaGetSymbolAddress((void**)&buf, g_buf);
    float* q1b  = buf + 0 * SZB;
    float* kb   = buf + 1 * SZB;
    float* vb   = buf + 2 * SZB;
    float* nq   = buf + 3 * SZB;
    float* nk   = buf + 4 * SZB;
    float* nv   = buf + 5 * SZB;
    float* oatt = buf + 6 * SZB;
    float* o1   = buf + 7 * SZB;
    float* q2b  = buf + 8 * SZB;
    float* S    = buf + 9 * SZB;

    const dim3 thr(256);
    const dim3 gproj(1024 / BN, 8192 / BM);        // 8 x 64
    const dim3 gattS(2048 / BN, 2048 / BM, 4);     // 16 x 16 x 4
    const dim3 gattO(1024 / BN, 2048 / BM, 4);     // 8 x 16 x 4
    const float invtemp = 1.0f / 32.0f;            // 1/sqrt(1024)
    const long long sLD = 2048ll * 1024;
    const long long sLL = 2048ll * 2048;

    // ---------------- layer 1 ----------------
    gemm_k<false, true><<<gproj, thr>>>(q, Wq1, bq1, q1b, 8192, 1024, 1024, 1.f, 0, 0, 0);
    gemm_k<false, true><<<gproj, thr>>>(k, Wk1, bk1, kb, 8192, 1024, 1024, 1.f, 0, 0, 0);
    gemm_k<false, true><<<gproj, thr>>>(v, Wv1, bv1, vb, 8192, 1024, 1024, 1.f, 0, 0, 0);

    ln_k<<<8192, 256>>>(q1b, gq1, Bq1, nq);
    ln_k<<<8192, 256>>>(kb,  gk1, Bk1, nk);
    ln_k<<<8192, 256>>>(vb,  gv1, Bv1, nv);

    gemm_k<true, false><<<gattS, thr>>>(nq, nk, nullptr, S, 2048, 2048, 1024, invtemp, sLD, sLD, sLL);
    softmax_k<<<8192, 256>>>(S);
    gemm_k<false, false><<<gattO, thr>>>(S, nv, nullptr, oatt, 2048, 1024, 2048, 1.f, sLL, sLD, sLD);
    gemm_k<false, true><<<gproj, thr>>>(oatt, Wf1, bf1, o1, 8192, 1024, 1024, 1.f, 0, 0, 0);

    // ---------------- layer 2 ----------------
    gemm_k<false, true><<<gproj, thr>>>(o1, Wq2, bq2, q2b, 8192, 1024, 1024, 1.f, 0, 0, 0);
    gemm_k<false, true><<<gproj, thr>>>(k,  Wk2, bk2, kb,  8192, 1024, 1024, 1.f, 0, 0, 0);
    gemm_k<false, true><<<gproj, thr>>>(v,  Wv2, bv2, vb,  8192, 1024, 1024, 1.f, 0, 0, 0);

    ln_k<<<8192, 256>>>(q2b, gq2, Bq2, nq);
    ln_k<<<8192, 256>>>(kb,  gk2, Bk2, nk);
    ln_k<<<8192, 256>>>(vb,  gv2, Bv2, nv);

    // logits directly into a2 output region, softmax in place
    gemm_k<true, false><<<gattS, thr>>>(nq, nk, nullptr, a2, 2048, 2048, 1024, invtemp, sLD, sLD, sLL);
    softmax_k<<<8192, 256>>>(a2);
    gemm_k<false, false><<<gattO, thr>>>(a2, nv, nullptr, oatt, 2048, 1024, 2048, 1.f, sLL, sLD, sLD);
    gemm_k<false, true><<<gproj, thr>>>(oatt, Wf2, bf2, out, 8192, 1024, 1024, 1.f, 0, 0, 0);

    // residual concat
    res_k<<<(8192 * 2048 / 4) / 256, 256>>>(q1b, q2b, res);
}

// round 3
// speedup vs baseline: 2.4752x; 2.4752x over previous
#include <cuda_runtime.h>
#include <cuda_bf16.h>
#include <cstdint>

// ---------------------------------------------------------------------------
// B=4, L=2048, D=1024, fp32. Outputs: out(8.39M) | res(16.78M) | a2(16.78M).
// GEMMs via legacy mma.sync bf16 (sm_80 path, valid on compute_103) with
// 2-term bf16 split (3 products) for fp32-class accuracy.
// ---------------------------------------------------------------------------

#define SZB 8388608ll      // 8192*1024 elements
#define SSB 16777216ll     // 4*2048*2048 elements
#define WSZ 1048576ll      // 1024*1024 elements

__device__ float g_buf[151000064ull];   // 604MB scratch pool

using bf16 = __nv_bfloat16;

__device__ __forceinline__ uint32_t smem_u32(const void* p){
    uint32_t a;
    asm("{ .reg .u64 t; cvta.to.shared.u64 t, %1; cvt.u32.u64 %0, t; }" : "=r"(a) : "l"(p));
    return a;
}
__device__ __forceinline__ uint32_t pack2(float x, float y){
    __nv_bfloat162 t = __floats2bfloat162_rn(x, y);
    return *(uint32_t*)&t;
}
__device__ __forceinline__ void split1(float x, float& h, float& l){
    h = __bfloat162float(__float2bfloat16(x));
    l = x - h;
}

#define LDSM4(R, addr) \
    asm volatile("ldmatrix.sync.aligned.m8n8.x4.shared.b16 {%0,%1,%2,%3}, [%4];" \
        : "=r"((R)[0]), "=r"((R)[1]), "=r"((R)[2]), "=r"((R)[3]) : "r"(addr))

#define MMA16816(d, a, b) \
    asm volatile("mma.sync.aligned.m16n8k16.row.col.f32.bf16.bf16.f32 " \
        "{%0,%1,%2,%3}, {%4,%5,%6,%7}, {%8,%9}, {%0,%1,%2,%3};" \
        : "+f"((d)[0]), "+f"((d)[1]), "+f"((d)[2]), "+f"((d)[3]) \
        : "r"((a)[0]), "r"((a)[1]), "r"((a)[2]), "r"((a)[3]), "r"((b)[0]), "r"((b)[1]))

#define CP_ASYNC16(dst, src) \
    asm volatile("cp.async.cg.shared.global [%0], [%1], 16;" :: "r"(dst), "l"(src))

// ---------------------------------------------------------------------------
// GEMM: C = scale*(A @ B^T) (+bias).  A=(Ah,Al)[M,K] bf16, B=(Bh,Bl)[N,K] bf16.
// Products: AhBh + AhBl + AlBh.  OM bit0: fp32 C; bit1: bf16 split (Ch,Cl).
// 128x128 tile, BK=32, 4-stage cp.async, 8 warps (2x4), warp tile 64x32.
// ---------------------------------------------------------------------------
constexpr int TPAD  = 80;                 // padded row stride bytes (32 bf16 = 64B data)
constexpr int TILEB = 128 * TPAD;         // 10240
constexpr int STGB  = 4 * TILEB;          // 40960
constexpr int SMEMB = 4 * STGB;           // 163840

template<int OM, bool BIAS>
__global__ void __launch_bounds__(256, 1) gemm_bf3(
    const bf16* __restrict__ Ah, const bf16* __restrict__ Al,
    const bf16* __restrict__ Bh, const bf16* __restrict__ Bl,
    const float* __restrict__ bias,
    float* __restrict__ Cf, bf16* __restrict__ Ch, bf16* __restrict__ Cl,
    int M, int N, int K, float scale,
    long long sA, long long sB, long long sC)
{
    extern __shared__ char sm[];
    const uint32_t sb = smem_u32(sm);
    const int tid = threadIdx.x, lane = tid & 31, warp = tid >> 5;
    const int wm = warp >> 2, wn = warp & 3;
    const int bz = blockIdx.z;
    Ah += bz * sA;  Al += bz * sA;
    Bh += bz * sB;  Bl += bz * sB;
    const long long co = (long long)bz * sC;
    const int m0 = blockIdx.y * 128, n0 = blockIdx.x * 128;

    auto load_stage = [&](int slot, int k0){
        const uint32_t s = sb + slot * STGB;
        const bf16* srcs[4] = {Ah, Al, Bh, Bl};
#pragma unroll
        for (int t = 0; t < 4; t++) {
            const bf16* src = srcs[t];
            const int rbase = (t < 2) ? m0 : n0;
#pragma unroll
            for (int i = 0; i < 2; i++) {
                const int c = tid + i * 256;          // 0..511
                const int row = c >> 2, s4 = c & 3;
                const uint32_t dst = s + t * TILEB + row * TPAD + s4 * 16;
                const bf16* g = src + (long long)(rbase + row) * K + k0 + s4 * 8;
                CP_ASYNC16(dst, g);
            }
        }
    };

    const int NS = K / 32;
    for (int p = 0; p < 3; p++) {
        load_stage(p, p * 32);
        asm volatile("cp.async.commit_group;" ::: "memory");
    }

    float acc[4][4][4] = {};

    for (int s = 0; s < NS; s++) {
        asm volatile("cp.async.wait_group 2;" ::: "memory");
        __syncthreads();
        if (s + 3 < NS) load_stage((s + 3) & 3, (s + 3) * 32);
        asm volatile("cp.async.commit_group;" ::: "memory");

        const uint32_t st  = sb + (s & 3) * STGB;
        const uint32_t tAh = st, tAl = st + TILEB, tBh = st + 2*TILEB, tBl = st + 3*TILEB;

#pragma unroll
        for (int ks = 0; ks < 2; ks++) {
            const int kb = ks * 32;   // byte offset of 16-elem k slab
            uint32_t ah[4][4], al[4][4], bh[4][2], bl[4][2];
#pragma unroll
            for (int mi = 0; mi < 4; mi++) {
                const uint32_t r   = wm * 64 + mi * 16 + (lane & 15);
                const uint32_t byo = kb + ((lane >> 4) << 4);
                LDSM4(ah[mi], tAh + r * TPAD + byo);
                LDSM4(al[mi], tAl + r * TPAD + byo);
            }
#pragma unroll
            for (int pi = 0; pi < 2; pi++) {
                const uint32_t r   = wn * 32 + pi * 16 + (lane & 7) + ((lane >> 4) << 3);
                const uint32_t byo = kb + (((lane >> 3) & 1) << 4);
                uint32_t v[4];
                LDSM4(v, tBh + r * TPAD + byo);
                bh[2*pi][0] = v[0]; bh[2*pi][1] = v[1];
                bh[2*pi+1][0] = v[2]; bh[2*pi+1][1] = v[3];
                LDSM4(v, tBl + r * TPAD + byo);
                bl[2*pi][0] = v[0]; bl[2*pi][1] = v[1];
                bl[2*pi+1][0] = v[2]; bl[2*pi+1][1] = v[3];
            }
#pragma unroll
            for (int mi = 0; mi < 4; mi++)
#pragma unroll
                for (int ni = 0; ni < 4; ni++) {
                    MMA16816(acc[mi][ni], ah[mi], bh[ni]);
                    MMA16816(acc[mi][ni], ah[mi], bl[ni]);
                    MMA16816(acc[mi][ni], al[mi], bh[ni]);
                }
        }
    }

    // epilogue
#pragma unroll
    for (int mi = 0; mi < 4; mi++) {
        const int r0 = m0 + wm * 64 + mi * 16 + (lane >> 2);
#pragma unroll
        for (int ni = 0; ni < 4; ni++) {
            const int col = n0 + wn * 32 + ni * 8 + (lane & 3) * 2;
            float b0 = 0.f, b1 = 0.f;
            if (BIAS) { b0 = __ldg(bias + col); b1 = __ldg(bias + col + 1); }
            const float x0 = acc[mi][ni][0] * scale + b0;
            const float x1 = acc[mi][ni][1] * scale + b1;
            const float x2 = acc[mi][ni][2] * scale + b0;
            const float x3 = acc[mi][ni][3] * scale + b1;
            const long long g0 = co + (long long)r0 * N + col;
            const long long g1 = co + (long long)(r0 + 8) * N + col;
            if (OM & 1) {
                *(float2*)(Cf + g0) = make_float2(x0, x1);
                *(float2*)(Cf + g1) = make_float2(x2, x3);
            }
            if (OM & 2) {
                float h0, l0, h1, l1, h2, l2, h3, l3;
                split1(x0, h0, l0); split1(x1, h1, l1);
                split1(x2, h2, l2); split1(x3, h3, l3);
                *(uint32_t*)(Ch + g0) = pack2(h0, h1);
                *(uint32_t*)(Ch + g1) = pack2(h2, h3);
                *(uint32_t*)(Cl + g0) = pack2(l0, l1);
                *(uint32_t*)(Cl + g1) = pack2(l2, l3);
            }
        }
    }
}

// ---------------------------------------------------------------------------
// fp32 -> bf16 hi/lo split
// ---------------------------------------------------------------------------
__global__ void __launch_bounds__(256) split_k(
    const float* __restrict__ x, bf16* __restrict__ h, bf16* __restrict__ l)
{
    const long long i = ((long long)blockIdx.x * 256 + threadIdx.x) * 4;
    const float4 v = *(const float4*)(x + i);
    float h0,l0,h1,l1,h2,l2,h3,l3;
    split1(v.x,h0,l0); split1(v.y,h1,l1); split1(v.z,h2,l2); split1(v.w,h3,l3);
    uint2 hp, lp;
    hp.x = pack2(h0,h1); hp.y = pack2(h2,h3);
    lp.x = pack2(l0,l1); lp.y = pack2(l2,l3);
    *(uint2*)(h + i) = hp;
    *(uint2*)(l + i) = lp;
}

// ---------------------------------------------------------------------------
// transpose + split: X[R,C] fp32 -> T[C,R] bf16 hi/lo
// ---------------------------------------------------------------------------
__global__ void __launch_bounds__(256) tspb_k(
    const float* __restrict__ X, bf16* __restrict__ Th, bf16* __restrict__ Tl,
    int R, int C, long long sIn, long long sOut)
{
    __shared__ float t[32][33];
    X  += (long long)blockIdx.z * sIn;
    Th += (long long)blockIdx.z * sOut;
    Tl += (long long)blockIdx.z * sOut;
    const int c0 = blockIdx.x * 32, r0 = blockIdx.y * 32;
    const int tx = threadIdx.x, ty = threadIdx.y;       // (32,8)
#pragma unroll
    for (int i = 0; i < 4; i++)
        t[ty + i * 8][tx] = X[(long long)(r0 + ty + i * 8) * C + c0 + tx];
    __syncthreads();
#pragma unroll
    for (int i = 0; i < 4; i++) {
        const float v = t[tx][ty + i * 8];
        float h, l; split1(v, h, l);
        const long long g = (long long)(c0 + ty + i * 8) * R + r0 + tx;
        Th[g] = __float2bfloat16(h);
        Tl[g] = __float2bfloat16(l);
    }
}

// ---------------------------------------------------------------------------
// LayerNorm rows of 1024. SPLIT: bf16 hi/lo out; else fp32 out.
// ---------------------------------------------------------------------------
template<bool SPLIT>
__global__ void __launch_bounds__(256) ln_k(
    const float* __restrict__ x, const float* __restrict__ g,
    const float* __restrict__ b, void* __restrict__ y0, void* __restrict__ y1)
{
    const long long row = blockIdx.x;
    const float4 v = ((const float4*)(x + row * 1024))[threadIdx.x];

    float s  = v.x + v.y + v.z + v.w;
    float s2 = v.x*v.x + v.y*v.y + v.z*v.z + v.w*v.w;
    __shared__ float sh[8], sh2[8];
#pragma unroll
    for (int o = 16; o > 0; o >>= 1) {
        s  += __shfl_xor_sync(0xffffffffu, s, o);
        s2 += __shfl_xor_sync(0xffffffffu, s2, o);
    }
    const int lane = threadIdx.x & 31, warp = threadIdx.x >> 5;
    if (lane == 0) { sh[warp] = s; sh2[warp] = s2; }
    __syncthreads();
    float S = 0.f, S2 = 0.f;
#pragma unroll
    for (int i = 0; i < 8; i++) { S += sh[i]; S2 += sh2[i]; }
    const float mean = S * (1.0f / 1024.0f);
    const float var  = S2 * (1.0f / 1024.0f) - mean * mean;
    const float inv  = rsqrtf(var + 1e-6f);

    const float4 gg = ((const float4*)g)[threadIdx.x];
    const float4 bb = ((const float4*)b)[threadIdx.x];
    float4 o;
    o.x = (v.x - mean) * inv * gg.x + bb.x;
    o.y = (v.y - mean) * inv * gg.y + bb.y;
    o.z = (v.z - mean) * inv * gg.z + bb.z;
    o.w = (v.w - mean) * inv * gg.w + bb.w;
    if (SPLIT) {
        float h0,l0,h1,l1,h2,l2,h3,l3;
        split1(o.x,h0,l0); split1(o.y,h1,l1); split1(o.z,h2,l2); split1(o.w,h3,l3);
        uint2 hp, lp;
        hp.x = pack2(h0,h1); hp.y = pack2(h2,h3);
        lp.x = pack2(l0,l1); lp.y = pack2(l2,l3);
        ((uint2*)((bf16*)y0 + row * 1024))[threadIdx.x] = hp;
        ((uint2*)((bf16*)y1 + row * 1024))[threadIdx.x] = lp;
    } else {
        ((float4*)((float*)y0 + row * 1024))[threadIdx.x] = o;
    }
}

// ---------------------------------------------------------------------------
// row softmax (2048); writes bf16 split P; optionally fp32 back in place.
// ---------------------------------------------------------------------------
template<bool F32OUT>
__global__ void __launch_bounds__(256) softmax_k(
    float* __restrict__ S, bf16* __restrict__ Ph, bf16* __restrict__ Pl)
{
    const long long row = blockIdx.x;
    float* r = S + row * 2048;
    const int base = threadIdx.x * 8;

    float v[8];
    float4 a = *(const float4*)(r + base);
    float4 c = *(const float4*)(r + base + 4);
    v[0]=a.x; v[1]=a.y; v[2]=a.z; v[3]=a.w; v[4]=c.x; v[5]=c.y; v[6]=c.z; v[7]=c.w;

    float mx = v[0];
#pragma unroll
    for (int i = 1; i < 8; i++) mx = fmaxf(mx, v[i]);
    __shared__ float shm[8], shs[8];
#pragma unroll
    for (int o = 16; o > 0; o >>= 1) mx = fmaxf(mx, __shfl_xor_sync(0xffffffffu, mx, o));
    const int lane = threadIdx.x & 31, warp = threadIdx.x >> 5;
    if (lane == 0) shm[warp] = mx;
    __syncthreads();
    float M = shm[0];
#pragma unroll
    for (int i = 1; i < 8; i++) M = fmaxf(M, shm[i]);

    float sum = 0.f;
#pragma unroll
    for (int i = 0; i < 8; i++) { v[i] = __expf(v[i] - M); sum += v[i]; }
#pragma unroll
    for (int o = 16; o > 0; o >>= 1) sum += __shfl_xor_sync(0xffffffffu, sum, o);
    if (lane == 0) shs[warp] = sum;
    __syncthreads();
    float T = 0.f;
#pragma unroll
    for (int i = 0; i < 8; i++) T += shs[i];
    const float inv = 1.0f / T;

    uint4 hp, lp;
    float p0,p1,h0,l0,h1,l1;
    p0 = v[0]*inv; p1 = v[1]*inv; split1(p0,h0,l0); split1(p1,h1,l1);
    hp.x = pack2(h0,h1); lp.x = pack2(l0,l1); a.x = p0; a.y = p1;
    p0 = v[2]*inv; p1 = v[3]*inv; split1(p0,h0,l0); split1(p1,h1,l1);
    hp.y = pack2(h0,h1); lp.y = pack2(l0,l1); a.z = p0; a.w = p1;
    p0 = v[4]*inv; p1 = v[5]*inv; split1(p0,h0,l0); split1(p1,h1,l1);
    hp.z = pack2(h0,h1); lp.z = pack2(l0,l1); c.x = p0; c.y = p1;
    p0 = v[6]*inv; p1 = v[7]*inv; split1(p0,h0,l0); split1(p1,h1,l1);
    hp.w = pack2(h0,h1); lp.w = pack2(l0,l1); c.z = p0; c.w = p1;

    *(uint4*)(Ph + row * 2048 + base) = hp;
    *(uint4*)(Pl + row * 2048 + base) = lp;
    if (F32OUT) {
        *(float4*)(r + base)     = a;
        *(float4*)(r + base + 4) = c;
    }
}

// ---------------------------------------------------------------------------
__global__ void __launch_bounds__(256) res_k(
    const float* __restrict__ q1, const float* __restrict__ q2, float* __restrict__ res)
{
    const long long i = (long long)blockIdx.x * blockDim.x + threadIdx.x;
    const long long e = i * 4;
    const long long row = e >> 11;
    const int c = (int)(e & 2047);
    const float* src = (c < 1024) ? (q1 + row * 1024 + c) : (q2 + row * 1024 + (c - 1024));
    *(float4*)(res + e) = *(const float4*)src;
}

// ---------------------------------------------------------------------------
extern "C" void kernel_launch(void* const* d_in, const int* in_sizes, int n_in,
                              void* d_out, int out_size)
{
    const float* q = (const float*)d_in[0];
    const float* k = (const float*)d_in[1];
    const float* v = (const float*)d_in[2];
    const float* W[8]  = {(const float*)d_in[3],  (const float*)d_in[5],
                          (const float*)d_in[7],  (const float*)d_in[9],
                          (const float*)d_in[11], (const float*)d_in[13],
                          (const float*)d_in[15], (const float*)d_in[17]};
    const float* bW[8] = {(const float*)d_in[4],  (const float*)d_in[6],
                          (const float*)d_in[8],  (const float*)d_in[10],
                          (const float*)d_in[12], (const float*)d_in[14],
                          (const float*)d_in[16], (const float*)d_in[18]};
    const float* gq1 = (const float*)d_in[19]; const float* Bq1 = (const float*)d_in[20];
    const float* gk1 = (const float*)d_in[21]; const float* Bk1 = (const float*)d_in[22];
    const float* gv1 = (const float*)d_in[23]; const float* Bv1 = (const float*)d_in[24];
    const float* gq2 = (const float*)d_in[25]; const float* Bq2 = (const float*)d_in[26];
    const float* gk2 = (const float*)d_in[27]; const float* Bk2 = (const float*)d_in[28];
    const float* gv2 = (const float*)d_in[29]; const float* Bv2 = (const float*)d_in[30];

    float* out = (float*)d_out;
    float* res = out + SZB;
    float* a2  = res + SSB;

    float* buf = nullptr;
    cudaGetSymbolAddress((void**)&buf, g_buf);
    char* P = (char*)buf;
    auto takeB = [&](long long bytes){ char* r = P; P += bytes; return r; };
    bf16* q_h  = (bf16*)takeB(SZB*2); bf16* q_l  = (bf16*)takeB(SZB*2);
    bf16* k_h  = (bf16*)takeB(SZB*2); bf16* k_l  = (bf16*)takeB(SZB*2);
    bf16* v_h  = (bf16*)takeB(SZB*2); bf16* v_l  = (bf16*)takeB(SZB*2);
    float* q1b = (float*)takeB(SZB*4);
    float* kb  = (float*)takeB(SZB*4);
    float* vb  = (float*)takeB(SZB*4);
    float* q2b = (float*)takeB(SZB*4);
    bf16* nq_h = (bf16*)takeB(SZB*2); bf16* nq_l = (bf16*)takeB(SZB*2);
    bf16* nk_h = (bf16*)takeB(SZB*2); bf16* nk_l = (bf16*)takeB(SZB*2);
    float* nv  = (float*)takeB(SZB*4);
    bf16* nvT_h= (bf16*)takeB(SZB*2); bf16* nvT_l= (bf16*)takeB(SZB*2);
    bf16* oa_h = (bf16*)takeB(SZB*2); bf16* oa_l = (bf16*)takeB(SZB*2);
    bf16* o1_h = (bf16*)takeB(SZB*2); bf16* o1_l = (bf16*)takeB(SZB*2);
    float* Sbuf= (float*)takeB(SSB*4);
    bf16* P_h  = (bf16*)takeB(SSB*2); bf16* P_l  = (bf16*)takeB(SSB*2);
    bf16* WTp  = (bf16*)takeB(8ll * 2 * WSZ * 2);
    auto WTh = [&](int i){ return WTp + (long long)i * 2 * WSZ; };
    auto WTl = [&](int i){ return WTp + (long long)i * 2 * WSZ + WSZ; };

    cudaFuncSetAttribute(gemm_bf3<1,true >, cudaFuncAttributeMaxDynamicSharedMemorySize, SMEMB);
    cudaFuncSetAttribute(gemm_bf3<1,false>, cudaFuncAttributeMaxDynamicSharedMemorySize, SMEMB);
    cudaFuncSetAttribute(gemm_bf3<2,true >, cudaFuncAttributeMaxDynamicSharedMemorySize, SMEMB);
    cudaFuncSetAttribute(gemm_bf3<2,false>, cudaFuncAttributeMaxDynamicSharedMemorySize, SMEMB);

    const dim3 tb(32, 8);
    const dim3 gproj(1024/128, 8192/128, 1);     // 8 x 64
    const dim3 gS(2048/128, 2048/128, 4);        // 16 x 16 x 4
    const dim3 gO(1024/128, 2048/128, 4);        // 8 x 16 x 4
    const float it = 1.0f / 32.0f;
    const long long sLD = 2048ll*1024, sLL = 2048ll*2048, sDL = 1024ll*2048;

    // operand prep
    split_k<<<SZB/4/256, 256>>>(q, q_h, q_l);
    split_k<<<SZB/4/256, 256>>>(k, k_h, k_l);
    split_k<<<SZB/4/256, 256>>>(v, v_h, v_l);
    for (int i = 0; i < 8; i++)
        tspb_k<<<dim3(32,32,1), tb>>>(W[i], WTh(i), WTl(i), 1024, 1024, 0, 0);

    // ---------------- layer 1 ----------------
    gemm_bf3<1,true><<<gproj,256,SMEMB>>>(q_h,q_l, WTh(0),WTl(0), bW[0], q1b,0,0, 8192,1024,1024, 1.f, 0,0,0);
    gemm_bf3<1,true><<<gproj,256,SMEMB>>>(k_h,k_l, WTh(1),WTl(1), bW[1], kb, 0,0, 8192,1024,1024, 1.f, 0,0,0);
    gemm_bf3<1,true><<<gproj,256,SMEMB>>>(v_h,v_l, WTh(2),WTl(2), bW[2], vb, 0,0, 8192,1024,1024, 1.f, 0,0,0);

    ln_k<true ><<<8192,256>>>(q1b, gq1, Bq1, nq_h, nq_l);
    ln_k<true ><<<8192,256>>>(kb,  gk1, Bk1, nk_h, nk_l);
    ln_k<false><<<8192,256>>>(vb,  gv1, Bv1, nv, nullptr);
    tspb_k<<<dim3(32,64,4), tb>>>(nv, nvT_h, nvT_l, 2048, 1024, sLD, sLD);

    gemm_bf3<1,false><<<gS,256,SMEMB>>>(nq_h,nq_l, nk_h,nk_l, 0, Sbuf,0,0, 2048,2048,1024, it, sLD,sLD,sLL);
    softmax_k<false><<<8192,256>>>(Sbuf, P_h, P_l);
    gemm_bf3<2,false><<<gO,256,SMEMB>>>(P_h,P_l, nvT_h,nvT_l, 0, 0,oa_h,oa_l, 2048,1024,2048, 1.f, sLL,sDL,sLD);
    gemm_bf3<2,true ><<<gproj,256,SMEMB>>>(oa_h,oa_l, WTh(3),WTl(3), bW[3], 0,o1_h,o1_l, 8192,1024,1024, 1.f, 0,0,0);

    // ---------------- layer 2 ----------------
    gemm_bf3<1,true><<<gproj,256,SMEMB>>>(o1_h,o1_l, WTh(4),WTl(4), bW[4], q2b,0,0, 8192,1024,1024, 1.f, 0,0,0);
    gemm_bf3<1,true><<<gproj,256,SMEMB>>>(k_h,k_l,   WTh(5),WTl(5), bW[5], kb, 0,0, 8192,1024,1024, 1.f, 0,0,0);
    gemm_bf3<1,true><<<gproj,256,SMEMB>>>(v_h,v_l,   WTh(6),WTl(6), bW[6], vb, 0,0, 8192,1024,1024, 1.f, 0,0,0);

    ln_k<true ><<<8192,256>>>(q2b, gq2, Bq2, nq_h, nq_l);
    ln_k<true ><<<8192,256>>>(kb,  gk2, Bk2, nk_h, nk_l);
    ln_k<false><<<8192,256>>>(vb,  gv2, Bv2, nv, nullptr);
    tspb_k<<<dim3(32,64,4), tb>>>(nv, nvT_h, nvT_l, 2048, 1024, sLD, sLD);

    gemm_bf3<1,false><<<gS,256,SMEMB>>>(nq_h,nq_l, nk_h,nk_l, 0, a2,0,0, 2048,2048,1024, it, sLD,sLD,sLL);
    softmax_k<true><<<8192,256>>>(a2, P_h, P_l);
    gemm_bf3<2,false><<<gO,256,SMEMB>>>(P_h,P_l, nvT_h,nvT_l, 0, 0,oa_h,oa_l, 2048,1024,2048, 1.f, sLL,sDL,sLD);
    gemm_bf3<1,true ><<<gproj,256,SMEMB>>>(oa_h,oa_l, WTh(7),WTl(7), bW[7], out,0,0, 8192,1024,1024, 1.f, 0,0,0);

    res_k<<<(8192*2048/4)/256, 256>>>(q1b, q2b, res);
}